// round 1
// baseline (speedup 1.0000x reference)
#include <cuda_runtime.h>
#include <math.h>

// ---------------- problem constants ----------------
#define Bn    32
#define Hs    56
#define Ws_   56
#define Cc    192
#define WS    7
#define SS    3
#define NH    6
#define Nn    49          // WS*WS
#define HD    32          // C/NH
#define NW    64          // (H/WS)*(W/WS)
#define BW    2048        // Bn*NW  (number of windows total)
#define ROWS  100352      // BW*Nn == Bn*H*W
#define HID   768         // 4*C
#define SCALE 0.17677669529663687f   // 32^-0.5
#define LNEPS 1e-5f

// ---------------- scratch (no cudaMalloc allowed) ----------------
__device__ float g_xw[(size_t)ROWS * Cc];      // LN1'ed, windowed   (77 MB)
__device__ float g_qkv[(size_t)ROWS * 3 * Cc]; // qkv                (231 MB)
__device__ float g_ao[(size_t)ROWS * Cc];      // attention output   (77 MB)
__device__ float g_h[(size_t)ROWS * Cc];       // post-attn residual (77 MB)
__device__ float g_hid[(size_t)ROWS * HID];    // MLP hidden         (308 MB)

// ---------------- LN1 + roll(-3,-3) + window partition ----------------
__global__ void ln1_gather_kernel(const float* __restrict__ x,
                                  const float* __restrict__ g,
                                  const float* __restrict__ b,
                                  float* __restrict__ out) {
    int r = blockIdx.x * 8 + (threadIdx.x >> 5);
    if (r >= ROWS) return;
    int lane = threadIdx.x & 31;
    int b_ = r / Nn, t = r - b_ * Nn;
    int bb = b_ >> 6, w = b_ & 63;
    int hr = (w >> 3) * WS + t / WS;
    int wr = (w & 7) * WS + t % WS;
    int sh = hr + SS; if (sh >= Hs) sh -= Hs;
    int sw = wr + SS; if (sw >= Ws_) sw -= Ws_;
    const float* src = x + ((size_t)(bb * Hs * Ws_ + sh * Ws_ + sw)) * Cc;
    float v[6];
    float s = 0.f, s2 = 0.f;
    #pragma unroll
    for (int j = 0; j < 6; j++) {
        v[j] = src[lane + 32 * j];
        s += v[j]; s2 += v[j] * v[j];
    }
    #pragma unroll
    for (int o = 16; o; o >>= 1) {
        s  += __shfl_xor_sync(0xffffffffu, s,  o);
        s2 += __shfl_xor_sync(0xffffffffu, s2, o);
    }
    float mu = s * (1.f / Cc);
    float var = s2 * (1.f / Cc) - mu * mu;
    float rs = rsqrtf(var + LNEPS);
    float* dst = out + (size_t)r * Cc;
    #pragma unroll
    for (int j = 0; j < 6; j++) {
        int c = lane + 32 * j;
        dst[c] = (v[j] - mu) * rs * g[c] + b[c];
    }
}

// ---------------- plain LN (for norm2) ----------------
__global__ void ln_plain_kernel(const float* __restrict__ x,
                                const float* __restrict__ g,
                                const float* __restrict__ b,
                                float* __restrict__ out) {
    int r = blockIdx.x * 8 + (threadIdx.x >> 5);
    if (r >= ROWS) return;
    int lane = threadIdx.x & 31;
    const float* src = x + (size_t)r * Cc;
    float v[6];
    float s = 0.f, s2 = 0.f;
    #pragma unroll
    for (int j = 0; j < 6; j++) {
        v[j] = src[lane + 32 * j];
        s += v[j]; s2 += v[j] * v[j];
    }
    #pragma unroll
    for (int o = 16; o; o >>= 1) {
        s  += __shfl_xor_sync(0xffffffffu, s,  o);
        s2 += __shfl_xor_sync(0xffffffffu, s2, o);
    }
    float mu = s * (1.f / Cc);
    float var = s2 * (1.f / Cc) - mu * mu;
    float rs = rsqrtf(var + LNEPS);
    float* dst = out + (size_t)r * Cc;
    #pragma unroll
    for (int j = 0; j < 6; j++) {
        int c = lane + 32 * j;
        dst[c] = (v[j] - mu) * rs * g[c] + b[c];
    }
}

// ---------------- tiled SGEMM: C[M,N] = A[M,K] @ W[N,K]^T + bias, fused epilogues ----
// EPI 0: plain (+bias)                   -> Cout[r*N + c]
// EPI 1: +bias, exact GELU               -> Cout[r*N + c]
// EPI 2: +bias, window-reverse scatter + x residual -> Cout[dest]
// EPI 3: +bias, + resid[r*N+c]           -> Cout[r*N + c]
#define BM 128
#define BN 64
#define BK 16

template <int EPI>
__global__ __launch_bounds__(256) void gemm_kernel(
    const float* __restrict__ A, const float* __restrict__ Wm,
    const float* __restrict__ bias, float* __restrict__ Cout,
    int M, int N, int K,
    const float* __restrict__ resid) {
    __shared__ float As[BK][BM + 4];
    __shared__ float Bs[BK][BN + 4];

    int t = threadIdx.x;
    int tx = t & 15;         // n direction, 16 * 4 = 64
    int ty = t >> 4;         // m direction, 16 * 8 = 128
    int m0 = blockIdx.y * BM;
    int n0 = blockIdx.x * BN;

    float acc[8][4];
    #pragma unroll
    for (int i = 0; i < 8; i++)
        #pragma unroll
        for (int j = 0; j < 4; j++) acc[i][j] = 0.f;

    const int nk = K / BK;
    for (int kt = 0; kt < nk; kt++) {
        int k0 = kt * BK;
        // load A tile (BM x BK): 512 float4, 2 per thread
        #pragma unroll
        for (int l = 0; l < 2; l++) {
            int idx = t + l * 256;
            int row = idx >> 2, kq = idx & 3;
            float4 v = *(const float4*)(A + (size_t)(m0 + row) * K + k0 + kq * 4);
            As[kq * 4 + 0][row] = v.x;
            As[kq * 4 + 1][row] = v.y;
            As[kq * 4 + 2][row] = v.z;
            As[kq * 4 + 3][row] = v.w;
        }
        // load W tile (BN x BK): 256 float4, 1 per thread
        {
            int row = t >> 2, kq = t & 3;
            float4 v = *(const float4*)(Wm + (size_t)(n0 + row) * K + k0 + kq * 4);
            Bs[kq * 4 + 0][row] = v.x;
            Bs[kq * 4 + 1][row] = v.y;
            Bs[kq * 4 + 2][row] = v.z;
            Bs[kq * 4 + 3][row] = v.w;
        }
        __syncthreads();
        #pragma unroll
        for (int k = 0; k < BK; k++) {
            float4 a0 = *(const float4*)&As[k][ty * 8];
            float4 a1 = *(const float4*)&As[k][ty * 8 + 4];
            float4 bv = *(const float4*)&Bs[k][tx * 4];
            float am[8] = {a0.x, a0.y, a0.z, a0.w, a1.x, a1.y, a1.z, a1.w};
            float bn[4] = {bv.x, bv.y, bv.z, bv.w};
            #pragma unroll
            for (int i = 0; i < 8; i++)
                #pragma unroll
                for (int j = 0; j < 4; j++)
                    acc[i][j] = fmaf(am[i], bn[j], acc[i][j]);
        }
        __syncthreads();
    }

    // epilogue
    int cbase = n0 + tx * 4;
    float4 bv = *(const float4*)(bias + cbase);
    #pragma unroll
    for (int i = 0; i < 8; i++) {
        int r = m0 + ty * 8 + i;
        float4 c;
        c.x = acc[i][0] + bv.x;
        c.y = acc[i][1] + bv.y;
        c.z = acc[i][2] + bv.z;
        c.w = acc[i][3] + bv.w;
        if (EPI == 0) {
            *(float4*)(Cout + (size_t)r * N + cbase) = c;
        } else if (EPI == 1) {
            c.x = 0.5f * c.x * (1.f + erff(c.x * 0.7071067811865476f));
            c.y = 0.5f * c.y * (1.f + erff(c.y * 0.7071067811865476f));
            c.z = 0.5f * c.z * (1.f + erff(c.z * 0.7071067811865476f));
            c.w = 0.5f * c.w * (1.f + erff(c.w * 0.7071067811865476f));
            *(float4*)(Cout + (size_t)r * N + cbase) = c;
        } else if (EPI == 2) {
            // r -> (b_, token); window reverse + roll(+3,+3); add x
            int b_ = r / Nn, tok = r - b_ * Nn;
            int bb = b_ >> 6, w = b_ & 63;
            int hr = (w >> 3) * WS + tok / WS;
            int wr = (w & 7) * WS + tok % WS;
            int dh = hr + SS; if (dh >= Hs) dh -= Hs;
            int dw = wr + SS; if (dw >= Ws_) dw -= Ws_;
            size_t dest = ((size_t)(bb * Hs * Ws_ + dh * Ws_ + dw)) * Cc + cbase;
            float4 xr = *(const float4*)(resid + dest);
            c.x += xr.x; c.y += xr.y; c.z += xr.z; c.w += xr.w;
            *(float4*)(Cout + dest) = c;
        } else { // EPI == 3
            float4 xr = *(const float4*)(resid + (size_t)r * N + cbase);
            c.x += xr.x; c.y += xr.y; c.z += xr.z; c.w += xr.w;
            *(float4*)(Cout + (size_t)r * N + cbase) = c;
        }
    }
}

// ---------------- fused attention: scores + bias + mask + softmax + PV ----
// one block per (window b_, head), 128 threads
__global__ __launch_bounds__(128) void attn_kernel(
    const float* __restrict__ qkv, const float* __restrict__ rpb,
    float* __restrict__ out) {
    int blk = blockIdx.x;
    int head = blk % NH;
    int b_ = blk / NH;
    int w = b_ & 63;
    int wh = w >> 3, ww = w & 7;

    __shared__ float qs[Nn * HD];
    __shared__ float ks[Nn * HD];
    __shared__ float vs[Nn * HD];
    __shared__ float ss[Nn * 50];
    __shared__ float biasv[169];
    __shared__ int grp[Nn];

    int t = threadIdx.x;
    // load q,k,v for this (window, head)
    for (int i = t; i < Nn * HD; i += 128) {
        int row = i >> 5, d = i & 31;
        const float* base = qkv + ((size_t)(b_ * Nn + row)) * (3 * Cc) + head * HD + d;
        qs[i] = base[0];
        ks[i] = base[Cc];
        vs[i] = base[2 * Cc];
    }
    for (int i = t; i < 169; i += 128) biasv[i] = rpb[i * NH + head];
    if (t < Nn) {
        int hr = wh * WS + t / WS, wr = ww * WS + t % WS;
        int rh = hr < 49 ? 0 : (hr < 53 ? 1 : 2);
        int rw = wr < 49 ? 0 : (wr < 53 ? 1 : 2);
        grp[t] = rh * 3 + rw;
    }
    __syncthreads();

    // scores with bias + mask
    for (int idx = t; idx < Nn * Nn; idx += 128) {
        int i = idx / Nn, j = idx - i * Nn;
        const float4* qa = (const float4*)(qs + i * HD);
        const float4* ka = (const float4*)(ks + j * HD);
        float acc = 0.f;
        #pragma unroll
        for (int d4 = 0; d4 < 8; d4++) {
            float4 a = qa[d4], b = ka[d4];
            acc += a.x * b.x + a.y * b.y + a.z * b.z + a.w * b.w;
        }
        int ri = i / WS, ci = i - ri * WS;
        int rj = j / WS, cj = j - rj * WS;
        float bias = biasv[(ri - rj + 6) * 13 + (ci - cj + 6)];
        float msk = (grp[i] != grp[j]) ? -100.f : 0.f;
        ss[i * 50 + j] = acc * SCALE + bias + msk;
    }
    __syncthreads();

    // softmax per row (4 warps, strided rows)
    int warp = t >> 5, lane = t & 31;
    for (int i = warp; i < Nn; i += 4) {
        float a = ss[i * 50 + lane];
        float b = (lane + 32 < Nn) ? ss[i * 50 + lane + 32] : -1e30f;
        float mx = fmaxf(a, b);
        #pragma unroll
        for (int o = 16; o; o >>= 1) mx = fmaxf(mx, __shfl_xor_sync(0xffffffffu, mx, o));
        float e1 = __expf(a - mx);
        float e2 = (lane + 32 < Nn) ? __expf(b - mx) : 0.f;
        float sm = e1 + e2;
        #pragma unroll
        for (int o = 16; o; o >>= 1) sm += __shfl_xor_sync(0xffffffffu, sm, o);
        float inv = 1.f / sm;
        ss[i * 50 + lane] = e1 * inv;
        if (lane + 32 < Nn) ss[i * 50 + lane + 32] = e2 * inv;
    }
    __syncthreads();

    // O = P @ V   (49 x 32), vectorized over d
    for (int idx = t; idx < Nn * 8; idx += 128) {
        int i = idx >> 3, d4 = idx & 7;
        float4 acc = {0.f, 0.f, 0.f, 0.f};
        const float4* v4 = (const float4*)vs;
        #pragma unroll 7
        for (int j = 0; j < Nn; j++) {
            float p = ss[i * 50 + j];
            float4 vv = v4[j * 8 + d4];
            acc.x = fmaf(p, vv.x, acc.x);
            acc.y = fmaf(p, vv.y, acc.y);
            acc.z = fmaf(p, vv.z, acc.z);
            acc.w = fmaf(p, vv.w, acc.w);
        }
        *(float4*)(out + ((size_t)(b_ * Nn + i)) * Cc + head * HD + d4 * 4) = acc;
    }
}

// ---------------- launch ----------------
extern "C" void kernel_launch(void* const* d_in, const int* in_sizes, int n_in,
                              void* d_out, int out_size) {
    const float* x       = (const float*)d_in[0];
    const float* norm1_g = (const float*)d_in[1];
    const float* norm1_b = (const float*)d_in[2];
    const float* qkv_w   = (const float*)d_in[3];
    const float* qkv_b   = (const float*)d_in[4];
    const float* proj_w  = (const float*)d_in[5];
    const float* proj_b  = (const float*)d_in[6];
    const float* rpb     = (const float*)d_in[7];
    const float* norm2_g = (const float*)d_in[8];
    const float* norm2_b = (const float*)d_in[9];
    const float* fc1_w   = (const float*)d_in[10];
    const float* fc1_b   = (const float*)d_in[11];
    const float* fc2_w   = (const float*)d_in[12];
    const float* fc2_b   = (const float*)d_in[13];
    float* out = (float*)d_out;

    float *xw, *qkv, *ao, *h, *hid;
    cudaGetSymbolAddress((void**)&xw,  g_xw);
    cudaGetSymbolAddress((void**)&qkv, g_qkv);
    cudaGetSymbolAddress((void**)&ao,  g_ao);
    cudaGetSymbolAddress((void**)&h,   g_h);
    cudaGetSymbolAddress((void**)&hid, g_hid);

    // 1) LN1 + roll + window partition
    ln1_gather_kernel<<<ROWS / 8, 256>>>(x, norm1_g, norm1_b, xw);

    // 2) qkv = xw @ qkv_w^T + qkv_b         (100352 x 576, K=192)
    gemm_kernel<0><<<dim3(3 * Cc / BN, ROWS / BM), 256>>>(
        xw, qkv_w, qkv_b, qkv, ROWS, 3 * Cc, Cc, nullptr);

    // 3) fused attention
    attn_kernel<<<BW * NH, 128>>>(qkv, rpb, ao);

    // 4) proj + window reverse + roll + residual(x)  -> h
    gemm_kernel<2><<<dim3(Cc / BN, ROWS / BM), 256>>>(
        ao, proj_w, proj_b, h, ROWS, Cc, Cc, x);

    // 5) LN2 (reuse xw)
    ln_plain_kernel<<<ROWS / 8, 256>>>(h, norm2_g, norm2_b, xw);

    // 6) fc1 + GELU  (100352 x 768, K=192)
    gemm_kernel<1><<<dim3(HID / BN, ROWS / BM), 256>>>(
        xw, fc1_w, fc1_b, hid, ROWS, HID, Cc, nullptr);

    // 7) fc2 + residual(h) -> out  (100352 x 192, K=768)
    gemm_kernel<3><<<dim3(Cc / BN, ROWS / BM), 256>>>(
        hid, fc2_w, fc2_b, out, ROWS, Cc, HID, h);
}

// round 3
// speedup vs baseline: 2.2416x; 2.2416x over previous
#include <cuda_runtime.h>
#include <cuda_bf16.h>
#include <math.h>
#include <stdint.h>

// ---------------- problem constants ----------------
#define Bn    32
#define Hs    56
#define Ws_   56
#define Cc    192
#define WS    7
#define SS    3
#define NH    6
#define Nn    49
#define HD    32
#define BW    2048
#define ROWS  100352
#define HID   768
#define SCALE 0.17677669529663687f
#define LNEPS 1e-5f

// ---------------- helpers ----------------
__device__ __forceinline__ uint32_t smem_u32(const void* p) {
    uint32_t a;
    asm("{ .reg .u64 t; cvta.to.shared.u64 t, %1; cvt.u32.u64 %0, t; }" : "=r"(a) : "l"(p));
    return a;
}

#define LDSM4(r, a) \
    asm volatile("ldmatrix.sync.aligned.m8n8.x4.shared.b16 {%0,%1,%2,%3}, [%4];" \
        : "=r"((r)[0]), "=r"((r)[1]), "=r"((r)[2]), "=r"((r)[3]) : "r"(a))

#define MMA16816(d, a, b0, b1) \
    asm volatile("mma.sync.aligned.m16n8k16.row.col.f32.bf16.bf16.f32 " \
        "{%0,%1,%2,%3}, {%4,%5,%6,%7}, {%8,%9}, {%0,%1,%2,%3};" \
        : "+f"((d)[0]), "+f"((d)[1]), "+f"((d)[2]), "+f"((d)[3]) \
        : "r"((a)[0]), "r"((a)[1]), "r"((a)[2]), "r"((a)[3]), "r"(b0), "r"(b1))

__device__ __forceinline__ void split2(float v, __nv_bfloat16& h, __nv_bfloat16& l) {
    h = __float2bfloat16(v);
    l = __float2bfloat16(v - __bfloat162float(h));
}

// ---------------- scratch ----------------
__device__ __nv_bfloat16 g_xw_h[(size_t)ROWS * Cc];
__device__ __nv_bfloat16 g_xw_l[(size_t)ROWS * Cc];
__device__ float         g_qkv[(size_t)ROWS * 3 * Cc];
__device__ __nv_bfloat16 g_ao_h[(size_t)ROWS * Cc];
__device__ __nv_bfloat16 g_ao_l[(size_t)ROWS * Cc];
__device__ float         g_h[(size_t)ROWS * Cc];
__device__ __nv_bfloat16 g_hid_h[(size_t)ROWS * HID];
__device__ __nv_bfloat16 g_hid_l[(size_t)ROWS * HID];
__device__ __nv_bfloat16 g_wq_h[3 * Cc * Cc], g_wq_l[3 * Cc * Cc];
__device__ __nv_bfloat16 g_wp_h[Cc * Cc],     g_wp_l[Cc * Cc];
__device__ __nv_bfloat16 g_f1_h[HID * Cc],    g_f1_l[HID * Cc];
__device__ __nv_bfloat16 g_f2_h[Cc * HID],    g_f2_l[Cc * HID];

// ---------------- weight split ----------------
__global__ void convert_kernel(const float* __restrict__ w,
                               __nv_bfloat16* __restrict__ hi,
                               __nv_bfloat16* __restrict__ lo, int n) {
    int i = blockIdx.x * 256 + threadIdx.x;
    if (i < n) split2(w[i], hi[i], lo[i]);
}

// ---------------- LN kernels (write bf16 hi/lo) ----------------
__global__ void ln1_gather_kernel(const float* __restrict__ x,
                                  const float* __restrict__ g, const float* __restrict__ b,
                                  __nv_bfloat16* __restrict__ oh, __nv_bfloat16* __restrict__ ol) {
    int r = blockIdx.x * 8 + (threadIdx.x >> 5);
    if (r >= ROWS) return;
    int lane = threadIdx.x & 31;
    int b_ = r / Nn, t = r - b_ * Nn;
    int bb = b_ >> 6, w = b_ & 63;
    int hr = (w >> 3) * WS + t / WS;
    int wr = (w & 7) * WS + t % WS;
    int sh = hr + SS; if (sh >= Hs) sh -= Hs;
    int sw = wr + SS; if (sw >= Ws_) sw -= Ws_;
    const float* src = x + ((size_t)(bb * Hs * Ws_ + sh * Ws_ + sw)) * Cc;
    float v[6], s = 0.f, s2 = 0.f;
    #pragma unroll
    for (int j = 0; j < 6; j++) { v[j] = src[lane + 32 * j]; s += v[j]; s2 += v[j] * v[j]; }
    #pragma unroll
    for (int o = 16; o; o >>= 1) { s += __shfl_xor_sync(~0u, s, o); s2 += __shfl_xor_sync(~0u, s2, o); }
    float mu = s * (1.f / Cc), var = s2 * (1.f / Cc) - mu * mu;
    float rs = rsqrtf(var + LNEPS);
    size_t d0 = (size_t)r * Cc;
    #pragma unroll
    for (int j = 0; j < 6; j++) {
        int c = lane + 32 * j;
        float y = (v[j] - mu) * rs * g[c] + b[c];
        split2(y, oh[d0 + c], ol[d0 + c]);
    }
}

__global__ void ln_plain_kernel(const float* __restrict__ x,
                                const float* __restrict__ g, const float* __restrict__ b,
                                __nv_bfloat16* __restrict__ oh, __nv_bfloat16* __restrict__ ol) {
    int r = blockIdx.x * 8 + (threadIdx.x >> 5);
    if (r >= ROWS) return;
    int lane = threadIdx.x & 31;
    const float* src = x + (size_t)r * Cc;
    float v[6], s = 0.f, s2 = 0.f;
    #pragma unroll
    for (int j = 0; j < 6; j++) { v[j] = src[lane + 32 * j]; s += v[j]; s2 += v[j] * v[j]; }
    #pragma unroll
    for (int o = 16; o; o >>= 1) { s += __shfl_xor_sync(~0u, s, o); s2 += __shfl_xor_sync(~0u, s2, o); }
    float mu = s * (1.f / Cc), var = s2 * (1.f / Cc) - mu * mu;
    float rs = rsqrtf(var + LNEPS);
    size_t d0 = (size_t)r * Cc;
    #pragma unroll
    for (int j = 0; j < 6; j++) {
        int c = lane + 32 * j;
        float y = (v[j] - mu) * rs * g[c] + b[c];
        split2(y, oh[d0 + c], ol[d0 + c]);
    }
}

// ---------------- mma.sync bf16 GEMM with 3-term error compensation ----------
// C[M,N] = A@W^T (+bias, epilogues). A,W given as bf16 hi/lo pairs.
// Block tile 128x64, BK=32, 8 warps: warp grid 4(m) x 2(n), warp tile 32x32.
// EPI 0: fp32 +bias              -> Co
// EPI 1: +bias, GELU, split      -> Oh/Ol
// EPI 2: +bias, scatter+resid    -> Co
// EPI 3: +bias, +resid           -> Co
#define BKt   32
#define ASTR  40                       // 32 + 8 pad (bf16 elems)
#define OFF_AH 0
#define OFF_AL 10240
#define OFF_BH 20480
#define OFF_BL 25600
#define BUF_SZ 30720
#define SMEM_TOT (BUF_SZ * 2)          // 61440

template <int N_, int K_, int EPI>
__global__ __launch_bounds__(256) void gemm_mma(
    const __nv_bfloat16* __restrict__ Ah, const __nv_bfloat16* __restrict__ Al,
    const __nv_bfloat16* __restrict__ Wh, const __nv_bfloat16* __restrict__ Wl,
    const float* __restrict__ bias, float* __restrict__ Co,
    const float* __restrict__ resid,
    __nv_bfloat16* __restrict__ Oh, __nv_bfloat16* __restrict__ Ol) {
    extern __shared__ char smem[];
    const int t = threadIdx.x, lane = t & 31, wid = t >> 5;
    const int wm = wid & 3, wn = wid >> 2;
    const int m0 = blockIdx.y * 128, n0 = blockIdx.x * 64;
    constexpr int NKT = K_ / BKt;

    float acc[2][4][4];
    #pragma unroll
    for (int i = 0; i < 2; i++)
        #pragma unroll
        for (int j = 0; j < 4; j++)
            #pragma unroll
            for (int k = 0; k < 4; k++) acc[i][j][k] = 0.f;

    const int arow = t >> 2, akq = t & 3;        // A/B smem store coords
    // ---- prologue: tile 0 -> buffer 0 ----
    {
        #pragma unroll
        for (int l = 0; l < 2; l++) {
            int row = arow + l * 64;
            uint32_t so = (uint32_t)row * (ASTR * 2) + akq * 16;
            *(uint4*)(smem + OFF_AH + so) = *(const uint4*)(Ah + (size_t)(m0 + row) * K_ + akq * 8);
            *(uint4*)(smem + OFF_AL + so) = *(const uint4*)(Al + (size_t)(m0 + row) * K_ + akq * 8);
        }
        uint32_t so = (uint32_t)arow * (ASTR * 2) + akq * 16;
        *(uint4*)(smem + OFF_BH + so) = *(const uint4*)(Wh + (size_t)(n0 + arow) * K_ + akq * 8);
        *(uint4*)(smem + OFF_BL + so) = *(const uint4*)(Wl + (size_t)(n0 + arow) * K_ + akq * 8);
    }
    __syncthreads();

    const int fr = lane & 15;                    // ldmatrix row within 16
    const int fc = (lane >> 4) * 8;              // ldmatrix col half

    for (int kt = 0; kt < NKT; kt++) {
        char* buf = smem + (kt & 1) * BUF_SZ;
        uint4 pah[2], pal[2], pbh, pbl;
        if (kt + 1 < NKT) {
            int k0n = (kt + 1) * BKt;
            #pragma unroll
            for (int l = 0; l < 2; l++) {
                int row = arow + l * 64;
                pah[l] = *(const uint4*)(Ah + (size_t)(m0 + row) * K_ + k0n + akq * 8);
                pal[l] = *(const uint4*)(Al + (size_t)(m0 + row) * K_ + k0n + akq * 8);
            }
            pbh = *(const uint4*)(Wh + (size_t)(n0 + arow) * K_ + k0n + akq * 8);
            pbl = *(const uint4*)(Wl + (size_t)(n0 + arow) * K_ + k0n + akq * 8);
        }

        const uint32_t sAh = smem_u32(buf + OFF_AH);
        const uint32_t sAl = smem_u32(buf + OFF_AL);
        const uint32_t sBh = smem_u32(buf + OFF_BH);
        const uint32_t sBl = smem_u32(buf + OFF_BL);

        #pragma unroll
        for (int ks = 0; ks < 2; ks++) {
            int col = ks * 16 + fc;
            uint32_t ah[2][4], al[2][4], bh[2][4], bl[2][4];
            #pragma unroll
            for (int mf = 0; mf < 2; mf++) {
                uint32_t off = (uint32_t)(wm * 32 + mf * 16 + fr) * (ASTR * 2) + col * 2;
                LDSM4(ah[mf], sAh + off);
                LDSM4(al[mf], sAl + off);
            }
            #pragma unroll
            for (int nf2 = 0; nf2 < 2; nf2++) {
                uint32_t off = (uint32_t)(wn * 32 + nf2 * 16 + fr) * (ASTR * 2) + col * 2;
                LDSM4(bh[nf2], sBh + off);
                LDSM4(bl[nf2], sBl + off);
            }
            #pragma unroll
            for (int mf = 0; mf < 2; mf++)
                #pragma unroll
                for (int nf = 0; nf < 4; nf++) {
                    int n2 = nf >> 1, sel = nf & 1;
                    MMA16816(acc[mf][nf], ah[mf], bh[n2][sel], bh[n2][sel + 2]);
                    MMA16816(acc[mf][nf], ah[mf], bl[n2][sel], bl[n2][sel + 2]);
                    MMA16816(acc[mf][nf], al[mf], bh[n2][sel], bh[n2][sel + 2]);
                }
        }

        if (kt + 1 < NKT) {
            __syncthreads();
            char* nb = smem + ((kt + 1) & 1) * BUF_SZ;
            #pragma unroll
            for (int l = 0; l < 2; l++) {
                int row = arow + l * 64;
                uint32_t so = (uint32_t)row * (ASTR * 2) + akq * 16;
                *(uint4*)(nb + OFF_AH + so) = pah[l];
                *(uint4*)(nb + OFF_AL + so) = pal[l];
            }
            uint32_t so = (uint32_t)arow * (ASTR * 2) + akq * 16;
            *(uint4*)(nb + OFF_BH + so) = pbh;
            *(uint4*)(nb + OFF_BL + so) = pbl;
            __syncthreads();
        }
    }

    // ---- epilogue ----
    const int r_in = lane >> 2, c_in = (lane & 3) * 2;
    #pragma unroll
    for (int mf = 0; mf < 2; mf++) {
        #pragma unroll
        for (int rr = 0; rr < 2; rr++) {
            int m = m0 + wm * 32 + mf * 16 + r_in + rr * 8;
            size_t dbase;
            if (EPI == 2) {
                int b_ = m / Nn, tok = m - b_ * Nn;
                int bb = b_ >> 6, w = b_ & 63;
                int hr = (w >> 3) * WS + tok / WS;
                int wr = (w & 7) * WS + tok % WS;
                int dh = hr + SS; if (dh >= Hs) dh -= Hs;
                int dw = wr + SS; if (dw >= Ws_) dw -= Ws_;
                dbase = ((size_t)(bb * Hs * Ws_ + dh * Ws_ + dw)) * Cc;
            } else {
                dbase = (size_t)m * N_;
            }
            #pragma unroll
            for (int nf = 0; nf < 4; nf++) {
                int col = n0 + wn * 32 + nf * 8 + c_in;
                float2 bv = *(const float2*)(bias + col);
                float v0 = acc[mf][nf][rr * 2]     + bv.x;
                float v1 = acc[mf][nf][rr * 2 + 1] + bv.y;
                if (EPI == 0) {
                    *(float2*)(Co + dbase + col) = make_float2(v0, v1);
                } else if (EPI == 1) {
                    v0 = 0.5f * v0 * (1.f + erff(v0 * 0.7071067811865476f));
                    v1 = 0.5f * v1 * (1.f + erff(v1 * 0.7071067811865476f));
                    __nv_bfloat162 hh, ll;
                    split2(v0, hh.x, ll.x); split2(v1, hh.y, ll.y);
                    *(__nv_bfloat162*)(Oh + dbase + col) = hh;
                    *(__nv_bfloat162*)(Ol + dbase + col) = ll;
                } else {
                    float2 xr = *(const float2*)(resid + dbase + col);
                    *(float2*)(Co + dbase + col) = make_float2(v0 + xr.x, v1 + xr.y);
                }
            }
        }
    }
}

// ---------------- fused attention (fp32), writes bf16 hi/lo ----------------
__global__ __launch_bounds__(128) void attn_kernel(
    const float* __restrict__ qkv, const float* __restrict__ rpb,
    __nv_bfloat16* __restrict__ oh, __nv_bfloat16* __restrict__ ol) {
    int blk = blockIdx.x;
    int head = blk % NH;
    int b_ = blk / NH;
    int w = b_ & 63;
    int wh = w >> 3, ww = w & 7;

    __shared__ float qs[Nn * HD], ks[Nn * HD], vs[Nn * HD];
    __shared__ float ss[Nn * 50];
    __shared__ float biasv[169];
    __shared__ int grp[Nn];

    int t = threadIdx.x;
    for (int i = t; i < Nn * HD; i += 128) {
        int row = i >> 5, d = i & 31;
        const float* base = qkv + ((size_t)(b_ * Nn + row)) * (3 * Cc) + head * HD + d;
        qs[i] = base[0]; ks[i] = base[Cc]; vs[i] = base[2 * Cc];
    }
    for (int i = t; i < 169; i += 128) biasv[i] = rpb[i * NH + head];
    if (t < Nn) {
        int hr = wh * WS + t / WS, wr = ww * WS + t % WS;
        int rh = hr < 49 ? 0 : (hr < 53 ? 1 : 2);
        int rw = wr < 49 ? 0 : (wr < 53 ? 1 : 2);
        grp[t] = rh * 3 + rw;
    }
    __syncthreads();

    for (int idx = t; idx < Nn * Nn; idx += 128) {
        int i = idx / Nn, j = idx - i * Nn;
        const float4* qa = (const float4*)(qs + i * HD);
        const float4* ka = (const float4*)(ks + j * HD);
        float acc = 0.f;
        #pragma unroll
        for (int d4 = 0; d4 < 8; d4++) {
            float4 a = qa[d4], b = ka[d4];
            acc += a.x * b.x + a.y * b.y + a.z * b.z + a.w * b.w;
        }
        int ri = i / WS, ci = i - ri * WS;
        int rj = j / WS, cj = j - rj * WS;
        float bias = biasv[(ri - rj + 6) * 13 + (ci - cj + 6)];
        float msk = (grp[i] != grp[j]) ? -100.f : 0.f;
        ss[i * 50 + j] = acc * SCALE + bias + msk;
    }
    __syncthreads();

    int warp = t >> 5, lane = t & 31;
    for (int i = warp; i < Nn; i += 4) {
        float a = ss[i * 50 + lane];
        float b = (lane + 32 < Nn) ? ss[i * 50 + lane + 32] : -1e30f;
        float mx = fmaxf(a, b);
        #pragma unroll
        for (int o = 16; o; o >>= 1) mx = fmaxf(mx, __shfl_xor_sync(~0u, mx, o));
        float e1 = __expf(a - mx);
        float e2 = (lane + 32 < Nn) ? __expf(b - mx) : 0.f;
        float sm = e1 + e2;
        #pragma unroll
        for (int o = 16; o; o >>= 1) sm += __shfl_xor_sync(~0u, sm, o);
        float inv = 1.f / sm;
        ss[i * 50 + lane] = e1 * inv;
        if (lane + 32 < Nn) ss[i * 50 + lane + 32] = e2 * inv;
    }
    __syncthreads();

    for (int idx = t; idx < Nn * 8; idx += 128) {
        int i = idx >> 3, d4 = idx & 7;
        float4 acc = {0.f, 0.f, 0.f, 0.f};
        const float4* v4 = (const float4*)vs;
        #pragma unroll 7
        for (int j = 0; j < Nn; j++) {
            float p = ss[i * 50 + j];
            float4 vv = v4[j * 8 + d4];
            acc.x = fmaf(p, vv.x, acc.x);
            acc.y = fmaf(p, vv.y, acc.y);
            acc.z = fmaf(p, vv.z, acc.z);
            acc.w = fmaf(p, vv.w, acc.w);
        }
        size_t base = ((size_t)(b_ * Nn + i)) * Cc + head * HD + d4 * 4;
        __nv_bfloat162 h0, h1, l0, l1;
        split2(acc.x, h0.x, l0.x); split2(acc.y, h0.y, l0.y);
        split2(acc.z, h1.x, l1.x); split2(acc.w, h1.y, l1.y);
        *(__nv_bfloat162*)(oh + base)     = h0;
        *(__nv_bfloat162*)(oh + base + 2) = h1;
        *(__nv_bfloat162*)(ol + base)     = l0;
        *(__nv_bfloat162*)(ol + base + 2) = l1;
    }
}

// ---------------- launch ----------------
extern "C" void kernel_launch(void* const* d_in, const int* in_sizes, int n_in,
                              void* d_out, int out_size) {
    const float* x       = (const float*)d_in[0];
    const float* norm1_g = (const float*)d_in[1];
    const float* norm1_b = (const float*)d_in[2];
    const float* qkv_w   = (const float*)d_in[3];
    const float* qkv_b   = (const float*)d_in[4];
    const float* proj_w  = (const float*)d_in[5];
    const float* proj_b  = (const float*)d_in[6];
    const float* rpb     = (const float*)d_in[7];
    const float* norm2_g = (const float*)d_in[8];
    const float* norm2_b = (const float*)d_in[9];
    const float* fc1_w   = (const float*)d_in[10];
    const float* fc1_b   = (const float*)d_in[11];
    const float* fc2_w   = (const float*)d_in[12];
    const float* fc2_b   = (const float*)d_in[13];
    float* out = (float*)d_out;

    __nv_bfloat16 *xwh, *xwl, *aoh, *aol, *hidh, *hidl;
    __nv_bfloat16 *wqh, *wql, *wph, *wpl, *f1h, *f1l, *f2h, *f2l;
    float *qkv, *h;
    cudaGetSymbolAddress((void**)&xwh, g_xw_h);   cudaGetSymbolAddress((void**)&xwl, g_xw_l);
    cudaGetSymbolAddress((void**)&qkv, g_qkv);
    cudaGetSymbolAddress((void**)&aoh, g_ao_h);   cudaGetSymbolAddress((void**)&aol, g_ao_l);
    cudaGetSymbolAddress((void**)&h,   g_h);
    cudaGetSymbolAddress((void**)&hidh, g_hid_h); cudaGetSymbolAddress((void**)&hidl, g_hid_l);
    cudaGetSymbolAddress((void**)&wqh, g_wq_h);   cudaGetSymbolAddress((void**)&wql, g_wq_l);
    cudaGetSymbolAddress((void**)&wph, g_wp_h);   cudaGetSymbolAddress((void**)&wpl, g_wp_l);
    cudaGetSymbolAddress((void**)&f1h, g_f1_h);   cudaGetSymbolAddress((void**)&f1l, g_f1_l);
    cudaGetSymbolAddress((void**)&f2h, g_f2_h);   cudaGetSymbolAddress((void**)&f2l, g_f2_l);

    cudaFuncSetAttribute(gemm_mma<3 * Cc, Cc, 0>, cudaFuncAttributeMaxDynamicSharedMemorySize, SMEM_TOT);
    cudaFuncSetAttribute(gemm_mma<Cc, Cc, 2>,     cudaFuncAttributeMaxDynamicSharedMemorySize, SMEM_TOT);
    cudaFuncSetAttribute(gemm_mma<HID, Cc, 1>,    cudaFuncAttributeMaxDynamicSharedMemorySize, SMEM_TOT);
    cudaFuncSetAttribute(gemm_mma<Cc, HID, 3>,    cudaFuncAttributeMaxDynamicSharedMemorySize, SMEM_TOT);

    // weight splits
    convert_kernel<<<(3 * Cc * Cc + 255) / 256, 256>>>(qkv_w, wqh, wql, 3 * Cc * Cc);
    convert_kernel<<<(Cc * Cc + 255) / 256, 256>>>(proj_w, wph, wpl, Cc * Cc);
    convert_kernel<<<(HID * Cc + 255) / 256, 256>>>(fc1_w, f1h, f1l, HID * Cc);
    convert_kernel<<<(Cc * HID + 255) / 256, 256>>>(fc2_w, f2h, f2l, Cc * HID);

    // 1) LN1 + roll + window partition (bf16 hi/lo)
    ln1_gather_kernel<<<ROWS / 8, 256>>>(x, norm1_g, norm1_b, xwh, xwl);

    // 2) qkv GEMM (100352 x 576, K=192) -> fp32
    gemm_mma<3 * Cc, Cc, 0><<<dim3(9, ROWS / 128), 256, SMEM_TOT>>>(
        xwh, xwl, wqh, wql, qkv_b, qkv, nullptr, nullptr, nullptr);

    // 3) fused attention -> ao hi/lo
    attn_kernel<<<BW * NH, 128>>>(qkv, rpb, aoh, aol);

    // 4) proj GEMM + window reverse + roll + residual(x) -> h (fp32)
    gemm_mma<Cc, Cc, 2><<<dim3(3, ROWS / 128), 256, SMEM_TOT>>>(
        aoh, aol, wph, wpl, proj_b, h, x, nullptr, nullptr);

    // 5) LN2 -> bf16 hi/lo (reuse xw buffers)
    ln_plain_kernel<<<ROWS / 8, 256>>>(h, norm2_g, norm2_b, xwh, xwl);

    // 6) fc1 GEMM + GELU -> hid hi/lo (bf16)
    gemm_mma<HID, Cc, 1><<<dim3(12, ROWS / 128), 256, SMEM_TOT>>>(
        xwh, xwl, f1h, f1l, fc1_b, nullptr, nullptr, hidh, hidl);

    // 7) fc2 GEMM + residual(h) -> out (fp32)
    gemm_mma<Cc, HID, 3><<<dim3(3, ROWS / 128), 256, SMEM_TOT>>>(
        hidh, hidl, f2h, f2l, fc2_b, out, h, nullptr, nullptr);
}

// round 4
// speedup vs baseline: 3.3928x; 1.5135x over previous
#include <cuda_runtime.h>
#include <cuda_bf16.h>
#include <math.h>
#include <stdint.h>

// ---------------- problem constants ----------------
#define Bn    32
#define Hs    56
#define Ws_   56
#define Cc    192
#define WS    7
#define SS    3
#define NH    6
#define Nn    49
#define HD    32
#define BW    2048
#define ROWS  100352
#define HID   768
#define SCALE 0.17677669529663687f
#define LNEPS 1e-5f

// ---------------- helpers ----------------
__device__ __forceinline__ uint32_t smem_u32(const void* p) {
    uint32_t a;
    asm("{ .reg .u64 t; cvta.to.shared.u64 t, %1; cvt.u32.u64 %0, t; }" : "=r"(a) : "l"(p));
    return a;
}

#define LDSM4(r, a) \
    asm volatile("ldmatrix.sync.aligned.m8n8.x4.shared.b16 {%0,%1,%2,%3}, [%4];" \
        : "=r"((r)[0]), "=r"((r)[1]), "=r"((r)[2]), "=r"((r)[3]) : "r"(a))

#define MMA16816(d, a, b0, b1) \
    asm volatile("mma.sync.aligned.m16n8k16.row.col.f32.bf16.bf16.f32 " \
        "{%0,%1,%2,%3}, {%4,%5,%6,%7}, {%8,%9}, {%0,%1,%2,%3};" \
        : "+f"((d)[0]), "+f"((d)[1]), "+f"((d)[2]), "+f"((d)[3]) \
        : "r"((a)[0]), "r"((a)[1]), "r"((a)[2]), "r"((a)[3]), "r"(b0), "r"(b1))

__device__ __forceinline__ void split2(float v, __nv_bfloat16& h, __nv_bfloat16& l) {
    h = __float2bfloat16(v);
    l = __float2bfloat16(v - __bfloat162float(h));
}

// ---------------- scratch ----------------
__device__ __nv_bfloat16 g_xw_h[(size_t)ROWS * Cc];
__device__ __nv_bfloat16 g_xw_l[(size_t)ROWS * Cc];
__device__ float         g_qkv[(size_t)ROWS * 3 * Cc];
__device__ __nv_bfloat16 g_ao_h[(size_t)ROWS * Cc];
__device__ __nv_bfloat16 g_ao_l[(size_t)ROWS * Cc];
__device__ float         g_h[(size_t)ROWS * Cc];
__device__ __nv_bfloat16 g_hid_h[(size_t)ROWS * HID];
__device__ __nv_bfloat16 g_hid_l[(size_t)ROWS * HID];
__device__ __nv_bfloat16 g_wq_h[3 * Cc * Cc], g_wq_l[3 * Cc * Cc];
__device__ __nv_bfloat16 g_wp_h[Cc * Cc],     g_wp_l[Cc * Cc];
__device__ __nv_bfloat16 g_f1_h[HID * Cc],    g_f1_l[HID * Cc];
__device__ __nv_bfloat16 g_f2_h[Cc * HID],    g_f2_l[Cc * HID];

// ---------------- weight split ----------------
__global__ void convert_kernel(const float* __restrict__ w,
                               __nv_bfloat16* __restrict__ hi,
                               __nv_bfloat16* __restrict__ lo, int n) {
    int i = blockIdx.x * 256 + threadIdx.x;
    if (i < n) split2(w[i], hi[i], lo[i]);
}

// ---------------- LN kernels (write bf16 hi/lo) ----------------
__global__ void ln1_gather_kernel(const float* __restrict__ x,
                                  const float* __restrict__ g, const float* __restrict__ b,
                                  __nv_bfloat16* __restrict__ oh, __nv_bfloat16* __restrict__ ol) {
    int r = blockIdx.x * 8 + (threadIdx.x >> 5);
    if (r >= ROWS) return;
    int lane = threadIdx.x & 31;
    int b_ = r / Nn, t = r - b_ * Nn;
    int bb = b_ >> 6, w = b_ & 63;
    int hr = (w >> 3) * WS + t / WS;
    int wr = (w & 7) * WS + t % WS;
    int sh = hr + SS; if (sh >= Hs) sh -= Hs;
    int sw = wr + SS; if (sw >= Ws_) sw -= Ws_;
    const float* src = x + ((size_t)(bb * Hs * Ws_ + sh * Ws_ + sw)) * Cc;
    float v[6], s = 0.f, s2 = 0.f;
    #pragma unroll
    for (int j = 0; j < 6; j++) { v[j] = src[lane + 32 * j]; s += v[j]; s2 += v[j] * v[j]; }
    #pragma unroll
    for (int o = 16; o; o >>= 1) { s += __shfl_xor_sync(~0u, s, o); s2 += __shfl_xor_sync(~0u, s2, o); }
    float mu = s * (1.f / Cc), var = s2 * (1.f / Cc) - mu * mu;
    float rs = rsqrtf(var + LNEPS);
    size_t d0 = (size_t)r * Cc;
    #pragma unroll
    for (int j = 0; j < 6; j++) {
        int c = lane + 32 * j;
        float y = (v[j] - mu) * rs * g[c] + b[c];
        split2(y, oh[d0 + c], ol[d0 + c]);
    }
}

__global__ void ln_plain_kernel(const float* __restrict__ x,
                                const float* __restrict__ g, const float* __restrict__ b,
                                __nv_bfloat16* __restrict__ oh, __nv_bfloat16* __restrict__ ol) {
    int r = blockIdx.x * 8 + (threadIdx.x >> 5);
    if (r >= ROWS) return;
    int lane = threadIdx.x & 31;
    const float* src = x + (size_t)r * Cc;
    float v[6], s = 0.f, s2 = 0.f;
    #pragma unroll
    for (int j = 0; j < 6; j++) { v[j] = src[lane + 32 * j]; s += v[j]; s2 += v[j] * v[j]; }
    #pragma unroll
    for (int o = 16; o; o >>= 1) { s += __shfl_xor_sync(~0u, s, o); s2 += __shfl_xor_sync(~0u, s2, o); }
    float mu = s * (1.f / Cc), var = s2 * (1.f / Cc) - mu * mu;
    float rs = rsqrtf(var + LNEPS);
    size_t d0 = (size_t)r * Cc;
    #pragma unroll
    for (int j = 0; j < 6; j++) {
        int c = lane + 32 * j;
        float y = (v[j] - mu) * rs * g[c] + b[c];
        split2(y, oh[d0 + c], ol[d0 + c]);
    }
}

// ---------------- mma.sync bf16 GEMM with 3-term error compensation ----------
#define BKt   32
#define ASTR  40
#define OFF_AH 0
#define OFF_AL 10240
#define OFF_BH 20480
#define OFF_BL 25600
#define BUF_SZ 30720
#define SMEM_TOT (BUF_SZ * 2)

template <int N_, int K_, int EPI>
__global__ __launch_bounds__(256) void gemm_mma(
    const __nv_bfloat16* __restrict__ Ah, const __nv_bfloat16* __restrict__ Al,
    const __nv_bfloat16* __restrict__ Wh, const __nv_bfloat16* __restrict__ Wl,
    const float* __restrict__ bias, float* __restrict__ Co,
    const float* __restrict__ resid,
    __nv_bfloat16* __restrict__ Oh, __nv_bfloat16* __restrict__ Ol) {
    extern __shared__ char smem[];
    const int t = threadIdx.x, lane = t & 31, wid = t >> 5;
    const int wm = wid & 3, wn = wid >> 2;
    const int m0 = blockIdx.y * 128, n0 = blockIdx.x * 64;
    constexpr int NKT = K_ / BKt;

    float acc[2][4][4];
    #pragma unroll
    for (int i = 0; i < 2; i++)
        #pragma unroll
        for (int j = 0; j < 4; j++)
            #pragma unroll
            for (int k = 0; k < 4; k++) acc[i][j][k] = 0.f;

    const int arow = t >> 2, akq = t & 3;
    {
        #pragma unroll
        for (int l = 0; l < 2; l++) {
            int row = arow + l * 64;
            uint32_t so = (uint32_t)row * (ASTR * 2) + akq * 16;
            *(uint4*)(smem + OFF_AH + so) = *(const uint4*)(Ah + (size_t)(m0 + row) * K_ + akq * 8);
            *(uint4*)(smem + OFF_AL + so) = *(const uint4*)(Al + (size_t)(m0 + row) * K_ + akq * 8);
        }
        uint32_t so = (uint32_t)arow * (ASTR * 2) + akq * 16;
        *(uint4*)(smem + OFF_BH + so) = *(const uint4*)(Wh + (size_t)(n0 + arow) * K_ + akq * 8);
        *(uint4*)(smem + OFF_BL + so) = *(const uint4*)(Wl + (size_t)(n0 + arow) * K_ + akq * 8);
    }
    __syncthreads();

    const int fr = lane & 15;
    const int fc = (lane >> 4) * 8;

    for (int kt = 0; kt < NKT; kt++) {
        char* buf = smem + (kt & 1) * BUF_SZ;
        uint4 pah[2], pal[2], pbh, pbl;
        if (kt + 1 < NKT) {
            int k0n = (kt + 1) * BKt;
            #pragma unroll
            for (int l = 0; l < 2; l++) {
                int row = arow + l * 64;
                pah[l] = *(const uint4*)(Ah + (size_t)(m0 + row) * K_ + k0n + akq * 8);
                pal[l] = *(const uint4*)(Al + (size_t)(m0 + row) * K_ + k0n + akq * 8);
            }
            pbh = *(const uint4*)(Wh + (size_t)(n0 + arow) * K_ + k0n + akq * 8);
            pbl = *(const uint4*)(Wl + (size_t)(n0 + arow) * K_ + k0n + akq * 8);
        }

        const uint32_t sAh = smem_u32(buf + OFF_AH);
        const uint32_t sAl = smem_u32(buf + OFF_AL);
        const uint32_t sBh = smem_u32(buf + OFF_BH);
        const uint32_t sBl = smem_u32(buf + OFF_BL);

        #pragma unroll
        for (int ks = 0; ks < 2; ks++) {
            int col = ks * 16 + fc;
            uint32_t ah[2][4], al[2][4], bh[2][4], bl[2][4];
            #pragma unroll
            for (int mf = 0; mf < 2; mf++) {
                uint32_t off = (uint32_t)(wm * 32 + mf * 16 + fr) * (ASTR * 2) + col * 2;
                LDSM4(ah[mf], sAh + off);
                LDSM4(al[mf], sAl + off);
            }
            #pragma unroll
            for (int nf2 = 0; nf2 < 2; nf2++) {
                uint32_t off = (uint32_t)(wn * 32 + nf2 * 16 + fr) * (ASTR * 2) + col * 2;
                LDSM4(bh[nf2], sBh + off);
                LDSM4(bl[nf2], sBl + off);
            }
            #pragma unroll
            for (int mf = 0; mf < 2; mf++)
                #pragma unroll
                for (int nf = 0; nf < 4; nf++) {
                    int n2 = nf >> 1, sel = nf & 1;
                    MMA16816(acc[mf][nf], ah[mf], bh[n2][sel], bh[n2][sel + 2]);
                    MMA16816(acc[mf][nf], ah[mf], bl[n2][sel], bl[n2][sel + 2]);
                    MMA16816(acc[mf][nf], al[mf], bh[n2][sel], bh[n2][sel + 2]);
                }
        }

        if (kt + 1 < NKT) {
            __syncthreads();
            char* nb = smem + ((kt + 1) & 1) * BUF_SZ;
            #pragma unroll
            for (int l = 0; l < 2; l++) {
                int row = arow + l * 64;
                uint32_t so = (uint32_t)row * (ASTR * 2) + akq * 16;
                *(uint4*)(nb + OFF_AH + so) = pah[l];
                *(uint4*)(nb + OFF_AL + so) = pal[l];
            }
            uint32_t so = (uint32_t)arow * (ASTR * 2) + akq * 16;
            *(uint4*)(nb + OFF_BH + so) = pbh;
            *(uint4*)(nb + OFF_BL + so) = pbl;
            __syncthreads();
        }
    }

    const int r_in = lane >> 2, c_in = (lane & 3) * 2;
    #pragma unroll
    for (int mf = 0; mf < 2; mf++) {
        #pragma unroll
        for (int rr = 0; rr < 2; rr++) {
            int m = m0 + wm * 32 + mf * 16 + r_in + rr * 8;
            size_t dbase;
            if (EPI == 2) {
                int b_ = m / Nn, tok = m - b_ * Nn;
                int bb = b_ >> 6, w = b_ & 63;
                int hr = (w >> 3) * WS + tok / WS;
                int wr = (w & 7) * WS + tok % WS;
                int dh = hr + SS; if (dh >= Hs) dh -= Hs;
                int dw = wr + SS; if (dw >= Ws_) dw -= Ws_;
                dbase = ((size_t)(bb * Hs * Ws_ + dh * Ws_ + dw)) * Cc;
            } else {
                dbase = (size_t)m * N_;
            }
            #pragma unroll
            for (int nf = 0; nf < 4; nf++) {
                int col = n0 + wn * 32 + nf * 8 + c_in;
                float2 bv = *(const float2*)(bias + col);
                float v0 = acc[mf][nf][rr * 2]     + bv.x;
                float v1 = acc[mf][nf][rr * 2 + 1] + bv.y;
                if (EPI == 0) {
                    *(float2*)(Co + dbase + col) = make_float2(v0, v1);
                } else if (EPI == 1) {
                    v0 = 0.5f * v0 * (1.f + erff(v0 * 0.7071067811865476f));
                    v1 = 0.5f * v1 * (1.f + erff(v1 * 0.7071067811865476f));
                    __nv_bfloat162 hh, ll;
                    split2(v0, hh.x, ll.x); split2(v1, hh.y, ll.y);
                    *(__nv_bfloat162*)(Oh + dbase + col) = hh;
                    *(__nv_bfloat162*)(Ol + dbase + col) = ll;
                } else {
                    float2 xr = *(const float2*)(resid + dbase + col);
                    *(float2*)(Co + dbase + col) = make_float2(v0 + xr.x, v1 + xr.y);
                }
            }
        }
    }
}

// ---------------- fused attention v2: broadcast k/v, register q/acc ----------
// block = (window, head), 64 threads; lane t = score row i (active t<49)
__global__ __launch_bounds__(64) void attn_kernel(
    const float* __restrict__ qkv, const float* __restrict__ rpb,
    __nv_bfloat16* __restrict__ oh, __nv_bfloat16* __restrict__ ol) {
    int blk = blockIdx.x;
    int head = blk % NH;
    int b_ = blk / NH;
    int w = b_ & 63;
    int wh = w >> 3, ww = w & 7;

    __shared__ float ks[Nn * HD];
    __shared__ float vs[Nn * HD];
    __shared__ float ss[Nn * 50];
    __shared__ float biasv[169];
    __shared__ int grp[Nn];

    int t = threadIdx.x;
    // stage k, v into smem (coalesced float4)
    for (int idx = t; idx < Nn * 8; idx += 64) {
        int row = idx >> 3, d4 = idx & 7;
        const float* base = qkv + ((size_t)(b_ * Nn + row)) * (3 * Cc) + head * HD + d4 * 4;
        *(float4*)(ks + row * HD + d4 * 4) = *(const float4*)(base + Cc);
        *(float4*)(vs + row * HD + d4 * 4) = *(const float4*)(base + 2 * Cc);
    }
    for (int i = t; i < 169; i += 64) biasv[i] = rpb[i * NH + head];
    if (t < Nn) {
        int hr = wh * WS + t / WS, wr = ww * WS + t % WS;
        int rh = hr < 49 ? 0 : (hr < 53 ? 1 : 2);
        int rw = wr < 49 ? 0 : (wr < 53 ? 1 : 2);
        grp[t] = rh * 3 + rw;
    }
    __syncthreads();

    const int i = t;
    const bool act = (i < Nn);
    int ri = 0, ci = 0, gi = 0;
    if (act) { ri = i / WS; ci = i - ri * WS; gi = grp[i]; }

    // q row in registers
    float4 qv[8];
    if (act) {
        const float4* qsrc = (const float4*)(qkv + ((size_t)(b_ * Nn + i)) * (3 * Cc) + head * HD);
        #pragma unroll
        for (int d4 = 0; d4 < 8; d4++) qv[d4] = qsrc[d4];
    }

    // scores: broadcast k_j, per-lane q
    #pragma unroll 7
    for (int j = 0; j < Nn; j++) {
        const float4* kj = (const float4*)(ks + j * HD);
        float acc = 0.f;
        #pragma unroll
        for (int d4 = 0; d4 < 8; d4++) {
            float4 kk = kj[d4];
            acc += qv[d4].x * kk.x + qv[d4].y * kk.y + qv[d4].z * kk.z + qv[d4].w * kk.w;
        }
        if (act) {
            int rj = j / WS, cj = j - rj * WS;
            float bias = biasv[(ri - rj + 6) * 13 + (ci - cj + 6)];
            float msk = (gi != grp[j]) ? -100.f : 0.f;
            ss[i * 50 + j] = acc * SCALE + bias + msk;
        }
    }

    // per-lane softmax over own row (no sync needed: same lane wrote it)
    float inv = 0.f;
    if (act) {
        float mx = -1e30f;
        #pragma unroll 7
        for (int j = 0; j < Nn; j++) mx = fmaxf(mx, ss[i * 50 + j]);
        float sm = 0.f;
        #pragma unroll 7
        for (int j = 0; j < Nn; j++) {
            float e = __expf(ss[i * 50 + j] - mx);
            ss[i * 50 + j] = e;
            sm += e;
        }
        inv = 1.f / sm;
    }

    // PV: broadcast v_j, per-lane p
    float4 acc[8];
    #pragma unroll
    for (int d4 = 0; d4 < 8; d4++) acc[d4] = make_float4(0.f, 0.f, 0.f, 0.f);
    #pragma unroll 7
    for (int j = 0; j < Nn; j++) {
        const float4* vj = (const float4*)(vs + j * HD);
        float p = act ? ss[i * 50 + j] : 0.f;
        #pragma unroll
        for (int d4 = 0; d4 < 8; d4++) {
            float4 vv = vj[d4];
            acc[d4].x = fmaf(p, vv.x, acc[d4].x);
            acc[d4].y = fmaf(p, vv.y, acc[d4].y);
            acc[d4].z = fmaf(p, vv.z, acc[d4].z);
            acc[d4].w = fmaf(p, vv.w, acc[d4].w);
        }
    }

    if (act) {
        size_t base = ((size_t)(b_ * Nn + i)) * Cc + head * HD;
        #pragma unroll
        for (int d4 = 0; d4 < 8; d4++) {
            float4 o = acc[d4];
            o.x *= inv; o.y *= inv; o.z *= inv; o.w *= inv;
            __nv_bfloat162 h0, h1, l0, l1;
            split2(o.x, h0.x, l0.x); split2(o.y, h0.y, l0.y);
            split2(o.z, h1.x, l1.x); split2(o.w, h1.y, l1.y);
            *(__nv_bfloat162*)(oh + base + d4 * 4)     = h0;
            *(__nv_bfloat162*)(oh + base + d4 * 4 + 2) = h1;
            *(__nv_bfloat162*)(ol + base + d4 * 4)     = l0;
            *(__nv_bfloat162*)(ol + base + d4 * 4 + 2) = l1;
        }
    }
}

// ---------------- launch ----------------
extern "C" void kernel_launch(void* const* d_in, const int* in_sizes, int n_in,
                              void* d_out, int out_size) {
    const float* x       = (const float*)d_in[0];
    const float* norm1_g = (const float*)d_in[1];
    const float* norm1_b = (const float*)d_in[2];
    const float* qkv_w   = (const float*)d_in[3];
    const float* qkv_b   = (const float*)d_in[4];
    const float* proj_w  = (const float*)d_in[5];
    const float* proj_b  = (const float*)d_in[6];
    const float* rpb     = (const float*)d_in[7];
    const float* norm2_g = (const float*)d_in[8];
    const float* norm2_b = (const float*)d_in[9];
    const float* fc1_w   = (const float*)d_in[10];
    const float* fc1_b   = (const float*)d_in[11];
    const float* fc2_w   = (const float*)d_in[12];
    const float* fc2_b   = (const float*)d_in[13];
    float* out = (float*)d_out;

    __nv_bfloat16 *xwh, *xwl, *aoh, *aol, *hidh, *hidl;
    __nv_bfloat16 *wqh, *wql, *wph, *wpl, *f1h, *f1l, *f2h, *f2l;
    float *qkv, *h;
    cudaGetSymbolAddress((void**)&xwh, g_xw_h);   cudaGetSymbolAddress((void**)&xwl, g_xw_l);
    cudaGetSymbolAddress((void**)&qkv, g_qkv);
    cudaGetSymbolAddress((void**)&aoh, g_ao_h);   cudaGetSymbolAddress((void**)&aol, g_ao_l);
    cudaGetSymbolAddress((void**)&h,   g_h);
    cudaGetSymbolAddress((void**)&hidh, g_hid_h); cudaGetSymbolAddress((void**)&hidl, g_hid_l);
    cudaGetSymbolAddress((void**)&wqh, g_wq_h);   cudaGetSymbolAddress((void**)&wql, g_wq_l);
    cudaGetSymbolAddress((void**)&wph, g_wp_h);   cudaGetSymbolAddress((void**)&wpl, g_wp_l);
    cudaGetSymbolAddress((void**)&f1h, g_f1_h);   cudaGetSymbolAddress((void**)&f1l, g_f1_l);
    cudaGetSymbolAddress((void**)&f2h, g_f2_h);   cudaGetSymbolAddress((void**)&f2l, g_f2_l);

    cudaFuncSetAttribute(gemm_mma<3 * Cc, Cc, 0>, cudaFuncAttributeMaxDynamicSharedMemorySize, SMEM_TOT);
    cudaFuncSetAttribute(gemm_mma<Cc, Cc, 2>,     cudaFuncAttributeMaxDynamicSharedMemorySize, SMEM_TOT);
    cudaFuncSetAttribute(gemm_mma<HID, Cc, 1>,    cudaFuncAttributeMaxDynamicSharedMemorySize, SMEM_TOT);
    cudaFuncSetAttribute(gemm_mma<Cc, HID, 3>,    cudaFuncAttributeMaxDynamicSharedMemorySize, SMEM_TOT);

    convert_kernel<<<(3 * Cc * Cc + 255) / 256, 256>>>(qkv_w, wqh, wql, 3 * Cc * Cc);
    convert_kernel<<<(Cc * Cc + 255) / 256, 256>>>(proj_w, wph, wpl, Cc * Cc);
    convert_kernel<<<(HID * Cc + 255) / 256, 256>>>(fc1_w, f1h, f1l, HID * Cc);
    convert_kernel<<<(Cc * HID + 255) / 256, 256>>>(fc2_w, f2h, f2l, Cc * HID);

    ln1_gather_kernel<<<ROWS / 8, 256>>>(x, norm1_g, norm1_b, xwh, xwl);

    gemm_mma<3 * Cc, Cc, 0><<<dim3(9, ROWS / 128), 256, SMEM_TOT>>>(
        xwh, xwl, wqh, wql, qkv_b, qkv, nullptr, nullptr, nullptr);

    attn_kernel<<<BW * NH, 64>>>(qkv, rpb, aoh, aol);

    gemm_mma<Cc, Cc, 2><<<dim3(3, ROWS / 128), 256, SMEM_TOT>>>(
        aoh, aol, wph, wpl, proj_b, h, x, nullptr, nullptr);

    ln_plain_kernel<<<ROWS / 8, 256>>>(h, norm2_g, norm2_b, xwh, xwl);

    gemm_mma<HID, Cc, 1><<<dim3(12, ROWS / 128), 256, SMEM_TOT>>>(
        xwh, xwl, f1h, f1l, fc1_b, nullptr, nullptr, hidh, hidl);

    gemm_mma<Cc, HID, 3><<<dim3(3, ROWS / 128), 256, SMEM_TOT>>>(
        hidh, hidl, f2h, f2l, fc2_b, out, h, nullptr, nullptr);
}

// round 5
// speedup vs baseline: 3.4926x; 1.0294x over previous
#include <cuda_runtime.h>
#include <cuda_bf16.h>
#include <math.h>
#include <stdint.h>

// ---------------- problem constants ----------------
#define Bn    32
#define Hs    56
#define Ws_   56
#define Cc    192
#define WS    7
#define SS    3
#define NH    6
#define Nn    49
#define HD    32
#define BW    2048
#define ROWS  100352
#define HID   768
#define SCALE 0.17677669529663687f
#define LNEPS 1e-5f

// ---------------- helpers ----------------
__device__ __forceinline__ uint32_t smem_u32(const void* p) {
    uint32_t a;
    asm("{ .reg .u64 t; cvta.to.shared.u64 t, %1; cvt.u32.u64 %0, t; }" : "=r"(a) : "l"(p));
    return a;
}

#define LDSM4(r, a) \
    asm volatile("ldmatrix.sync.aligned.m8n8.x4.shared.b16 {%0,%1,%2,%3}, [%4];" \
        : "=r"((r)[0]), "=r"((r)[1]), "=r"((r)[2]), "=r"((r)[3]) : "r"(a))

#define MMA16816(d, a, b0, b1) \
    asm volatile("mma.sync.aligned.m16n8k16.row.col.f32.bf16.bf16.f32 " \
        "{%0,%1,%2,%3}, {%4,%5,%6,%7}, {%8,%9}, {%0,%1,%2,%3};" \
        : "+f"((d)[0]), "+f"((d)[1]), "+f"((d)[2]), "+f"((d)[3]) \
        : "r"((a)[0]), "r"((a)[1]), "r"((a)[2]), "r"((a)[3]), "r"(b0), "r"(b1))

__device__ __forceinline__ void split2(float v, __nv_bfloat16& h, __nv_bfloat16& l) {
    h = __float2bfloat16(v);
    l = __float2bfloat16(v - __bfloat162float(h));
}

// ---------------- scratch ----------------
__device__ __nv_bfloat16 g_xw_h[(size_t)ROWS * Cc];
__device__ __nv_bfloat16 g_xw_l[(size_t)ROWS * Cc];
__device__ float         g_qkv[(size_t)ROWS * 3 * Cc];
__device__ __nv_bfloat16 g_ao_h[(size_t)ROWS * Cc];
__device__ __nv_bfloat16 g_ao_l[(size_t)ROWS * Cc];
__device__ float         g_h[(size_t)ROWS * Cc];
__device__ __nv_bfloat16 g_hid_h[(size_t)ROWS * HID];
__device__ __nv_bfloat16 g_hid_l[(size_t)ROWS * HID];
__device__ __nv_bfloat16 g_wq_h[3 * Cc * Cc], g_wq_l[3 * Cc * Cc];
__device__ __nv_bfloat16 g_wp_h[Cc * Cc],     g_wp_l[Cc * Cc];
__device__ __nv_bfloat16 g_f1_h[HID * Cc],    g_f1_l[HID * Cc];
__device__ __nv_bfloat16 g_f2_h[Cc * HID],    g_f2_l[Cc * HID];

// ---------------- weight split ----------------
__global__ void convert_kernel(const float* __restrict__ w,
                               __nv_bfloat16* __restrict__ hi,
                               __nv_bfloat16* __restrict__ lo, int n) {
    int i = blockIdx.x * 256 + threadIdx.x;
    if (i < n) split2(w[i], hi[i], lo[i]);
}

// ---------------- LN kernels (write bf16 hi/lo) ----------------
__global__ void ln1_gather_kernel(const float* __restrict__ x,
                                  const float* __restrict__ g, const float* __restrict__ b,
                                  __nv_bfloat16* __restrict__ oh, __nv_bfloat16* __restrict__ ol) {
    int r = blockIdx.x * 8 + (threadIdx.x >> 5);
    if (r >= ROWS) return;
    int lane = threadIdx.x & 31;
    int b_ = r / Nn, t = r - b_ * Nn;
    int bb = b_ >> 6, w = b_ & 63;
    int hr = (w >> 3) * WS + t / WS;
    int wr = (w & 7) * WS + t % WS;
    int sh = hr + SS; if (sh >= Hs) sh -= Hs;
    int sw = wr + SS; if (sw >= Ws_) sw -= Ws_;
    const float* src = x + ((size_t)(bb * Hs * Ws_ + sh * Ws_ + sw)) * Cc;
    float v[6], s = 0.f, s2 = 0.f;
    #pragma unroll
    for (int j = 0; j < 6; j++) { v[j] = src[lane + 32 * j]; s += v[j]; s2 += v[j] * v[j]; }
    #pragma unroll
    for (int o = 16; o; o >>= 1) { s += __shfl_xor_sync(~0u, s, o); s2 += __shfl_xor_sync(~0u, s2, o); }
    float mu = s * (1.f / Cc), var = s2 * (1.f / Cc) - mu * mu;
    float rs = rsqrtf(var + LNEPS);
    size_t d0 = (size_t)r * Cc;
    #pragma unroll
    for (int j = 0; j < 6; j++) {
        int c = lane + 32 * j;
        float y = (v[j] - mu) * rs * g[c] + b[c];
        split2(y, oh[d0 + c], ol[d0 + c]);
    }
}

__global__ void ln_plain_kernel(const float* __restrict__ x,
                                const float* __restrict__ g, const float* __restrict__ b,
                                __nv_bfloat16* __restrict__ oh, __nv_bfloat16* __restrict__ ol) {
    int r = blockIdx.x * 8 + (threadIdx.x >> 5);
    if (r >= ROWS) return;
    int lane = threadIdx.x & 31;
    const float* src = x + (size_t)r * Cc;
    float v[6], s = 0.f, s2 = 0.f;
    #pragma unroll
    for (int j = 0; j < 6; j++) { v[j] = src[lane + 32 * j]; s += v[j]; s2 += v[j] * v[j]; }
    #pragma unroll
    for (int o = 16; o; o >>= 1) { s += __shfl_xor_sync(~0u, s, o); s2 += __shfl_xor_sync(~0u, s2, o); }
    float mu = s * (1.f / Cc), var = s2 * (1.f / Cc) - mu * mu;
    float rs = rsqrtf(var + LNEPS);
    size_t d0 = (size_t)r * Cc;
    #pragma unroll
    for (int j = 0; j < 6; j++) {
        int c = lane + 32 * j;
        float y = (v[j] - mu) * rs * g[c] + b[c];
        split2(y, oh[d0 + c], ol[d0 + c]);
    }
}

// ---------------- mma.sync bf16 GEMM with 3-term error compensation ----------
#define BKt   32
#define ASTR  40
#define OFF_AH 0
#define OFF_AL 10240
#define OFF_BH 20480
#define OFF_BL 25600
#define BUF_SZ 30720
#define SMEM_TOT (BUF_SZ * 2)

template <int N_, int K_, int EPI>
__global__ __launch_bounds__(256) void gemm_mma(
    const __nv_bfloat16* __restrict__ Ah, const __nv_bfloat16* __restrict__ Al,
    const __nv_bfloat16* __restrict__ Wh, const __nv_bfloat16* __restrict__ Wl,
    const float* __restrict__ bias, float* __restrict__ Co,
    const float* __restrict__ resid,
    __nv_bfloat16* __restrict__ Oh, __nv_bfloat16* __restrict__ Ol) {
    extern __shared__ char smem[];
    const int t = threadIdx.x, lane = t & 31, wid = t >> 5;
    const int wm = wid & 3, wn = wid >> 2;
    const int m0 = blockIdx.y * 128, n0 = blockIdx.x * 64;
    constexpr int NKT = K_ / BKt;

    float acc[2][4][4];
    #pragma unroll
    for (int i = 0; i < 2; i++)
        #pragma unroll
        for (int j = 0; j < 4; j++)
            #pragma unroll
            for (int k = 0; k < 4; k++) acc[i][j][k] = 0.f;

    const int arow = t >> 2, akq = t & 3;
    {
        #pragma unroll
        for (int l = 0; l < 2; l++) {
            int row = arow + l * 64;
            uint32_t so = (uint32_t)row * (ASTR * 2) + akq * 16;
            *(uint4*)(smem + OFF_AH + so) = *(const uint4*)(Ah + (size_t)(m0 + row) * K_ + akq * 8);
            *(uint4*)(smem + OFF_AL + so) = *(const uint4*)(Al + (size_t)(m0 + row) * K_ + akq * 8);
        }
        uint32_t so = (uint32_t)arow * (ASTR * 2) + akq * 16;
        *(uint4*)(smem + OFF_BH + so) = *(const uint4*)(Wh + (size_t)(n0 + arow) * K_ + akq * 8);
        *(uint4*)(smem + OFF_BL + so) = *(const uint4*)(Wl + (size_t)(n0 + arow) * K_ + akq * 8);
    }
    __syncthreads();

    const int fr = lane & 15;
    const int fc = (lane >> 4) * 8;

    for (int kt = 0; kt < NKT; kt++) {
        char* buf = smem + (kt & 1) * BUF_SZ;
        uint4 pah[2], pal[2], pbh, pbl;
        if (kt + 1 < NKT) {
            int k0n = (kt + 1) * BKt;
            #pragma unroll
            for (int l = 0; l < 2; l++) {
                int row = arow + l * 64;
                pah[l] = *(const uint4*)(Ah + (size_t)(m0 + row) * K_ + k0n + akq * 8);
                pal[l] = *(const uint4*)(Al + (size_t)(m0 + row) * K_ + k0n + akq * 8);
            }
            pbh = *(const uint4*)(Wh + (size_t)(n0 + arow) * K_ + k0n + akq * 8);
            pbl = *(const uint4*)(Wl + (size_t)(n0 + arow) * K_ + k0n + akq * 8);
        }

        const uint32_t sAh = smem_u32(buf + OFF_AH);
        const uint32_t sAl = smem_u32(buf + OFF_AL);
        const uint32_t sBh = smem_u32(buf + OFF_BH);
        const uint32_t sBl = smem_u32(buf + OFF_BL);

        #pragma unroll
        for (int ks = 0; ks < 2; ks++) {
            int col = ks * 16 + fc;
            uint32_t ah[2][4], al[2][4], bh[2][4], bl[2][4];
            #pragma unroll
            for (int mf = 0; mf < 2; mf++) {
                uint32_t off = (uint32_t)(wm * 32 + mf * 16 + fr) * (ASTR * 2) + col * 2;
                LDSM4(ah[mf], sAh + off);
                LDSM4(al[mf], sAl + off);
            }
            #pragma unroll
            for (int nf2 = 0; nf2 < 2; nf2++) {
                uint32_t off = (uint32_t)(wn * 32 + nf2 * 16 + fr) * (ASTR * 2) + col * 2;
                LDSM4(bh[nf2], sBh + off);
                LDSM4(bl[nf2], sBl + off);
            }
            // term-major ordering: 8 independent accumulators per term pass
            #pragma unroll
            for (int mf = 0; mf < 2; mf++)
                #pragma unroll
                for (int nf = 0; nf < 4; nf++) {
                    int n2 = nf >> 1, sel = nf & 1;
                    MMA16816(acc[mf][nf], ah[mf], bh[n2][sel], bh[n2][sel + 2]);
                }
            #pragma unroll
            for (int mf = 0; mf < 2; mf++)
                #pragma unroll
                for (int nf = 0; nf < 4; nf++) {
                    int n2 = nf >> 1, sel = nf & 1;
                    MMA16816(acc[mf][nf], ah[mf], bl[n2][sel], bl[n2][sel + 2]);
                }
            #pragma unroll
            for (int mf = 0; mf < 2; mf++)
                #pragma unroll
                for (int nf = 0; nf < 4; nf++) {
                    int n2 = nf >> 1, sel = nf & 1;
                    MMA16816(acc[mf][nf], al[mf], bh[n2][sel], bh[n2][sel + 2]);
                }
        }

        if (kt + 1 < NKT) {
            // stores target the buffer last READ in iteration kt-1; the sync at the
            // end of kt-1 already ordered those reads -> no extra sync needed here.
            char* nb = smem + ((kt + 1) & 1) * BUF_SZ;
            #pragma unroll
            for (int l = 0; l < 2; l++) {
                int row = arow + l * 64;
                uint32_t so = (uint32_t)row * (ASTR * 2) + akq * 16;
                *(uint4*)(nb + OFF_AH + so) = pah[l];
                *(uint4*)(nb + OFF_AL + so) = pal[l];
            }
            uint32_t so = (uint32_t)arow * (ASTR * 2) + akq * 16;
            *(uint4*)(nb + OFF_BH + so) = pbh;
            *(uint4*)(nb + OFF_BL + so) = pbl;
            __syncthreads();
        }
    }

    const int r_in = lane >> 2, c_in = (lane & 3) * 2;
    #pragma unroll
    for (int mf = 0; mf < 2; mf++) {
        #pragma unroll
        for (int rr = 0; rr < 2; rr++) {
            int m = m0 + wm * 32 + mf * 16 + r_in + rr * 8;
            size_t dbase;
            if (EPI == 2) {
                int b_ = m / Nn, tok = m - b_ * Nn;
                int bb = b_ >> 6, w = b_ & 63;
                int hr = (w >> 3) * WS + tok / WS;
                int wr = (w & 7) * WS + tok % WS;
                int dh = hr + SS; if (dh >= Hs) dh -= Hs;
                int dw = wr + SS; if (dw >= Ws_) dw -= Ws_;
                dbase = ((size_t)(bb * Hs * Ws_ + dh * Ws_ + dw)) * Cc;
            } else {
                dbase = (size_t)m * N_;
            }
            #pragma unroll
            for (int nf = 0; nf < 4; nf++) {
                int col = n0 + wn * 32 + nf * 8 + c_in;
                float2 bv = *(const float2*)(bias + col);
                float v0 = acc[mf][nf][rr * 2]     + bv.x;
                float v1 = acc[mf][nf][rr * 2 + 1] + bv.y;
                if (EPI == 0) {
                    *(float2*)(Co + dbase + col) = make_float2(v0, v1);
                } else if (EPI == 1) {
                    v0 = 0.5f * v0 * (1.f + erff(v0 * 0.7071067811865476f));
                    v1 = 0.5f * v1 * (1.f + erff(v1 * 0.7071067811865476f));
                    __nv_bfloat162 hh, ll;
                    split2(v0, hh.x, ll.x); split2(v1, hh.y, ll.y);
                    *(__nv_bfloat162*)(Oh + dbase + col) = hh;
                    *(__nv_bfloat162*)(Ol + dbase + col) = ll;
                } else {
                    float2 xr = *(const float2*)(resid + dbase + col);
                    *(float2*)(Co + dbase + col) = make_float2(v0 + xr.x, v1 + xr.y);
                }
            }
        }
    }
}

// ---------------- fused attention: broadcast k/v, register q/acc ----------
#define SSTR 51
__global__ __launch_bounds__(64) void attn_kernel(
    const float* __restrict__ qkv, const float* __restrict__ rpb,
    __nv_bfloat16* __restrict__ oh, __nv_bfloat16* __restrict__ ol) {
    int blk = blockIdx.x;
    int head = blk % NH;
    int b_ = blk / NH;
    int w = b_ & 63;
    int wh = w >> 3, ww = w & 7;

    __shared__ float ks[Nn * HD];
    __shared__ float vs[Nn * HD];
    __shared__ float ss[Nn * SSTR];
    __shared__ float biasv[169];
    __shared__ int grp[Nn];

    int t = threadIdx.x;
    for (int idx = t; idx < Nn * 8; idx += 64) {
        int row = idx >> 3, d4 = idx & 7;
        const float* base = qkv + ((size_t)(b_ * Nn + row)) * (3 * Cc) + head * HD + d4 * 4;
        *(float4*)(ks + row * HD + d4 * 4) = *(const float4*)(base + Cc);
        *(float4*)(vs + row * HD + d4 * 4) = *(const float4*)(base + 2 * Cc);
    }
    for (int i = t; i < 169; i += 64) biasv[i] = rpb[i * NH + head];
    if (t < Nn) {
        int hr = wh * WS + t / WS, wr = ww * WS + t % WS;
        int rh = hr < 49 ? 0 : (hr < 53 ? 1 : 2);
        int rw = wr < 49 ? 0 : (wr < 53 ? 1 : 2);
        grp[t] = rh * 3 + rw;
    }
    __syncthreads();

    const int i = t;
    const bool act = (i < Nn);
    int ri = 0, ci = 0, gi = 0;
    if (act) { ri = i / WS; ci = i - ri * WS; gi = grp[i]; }

    float4 qv[8];
    if (act) {
        const float4* qsrc = (const float4*)(qkv + ((size_t)(b_ * Nn + i)) * (3 * Cc) + head * HD);
        #pragma unroll
        for (int d4 = 0; d4 < 8; d4++) qv[d4] = qsrc[d4];
    }

    #pragma unroll 7
    for (int j = 0; j < Nn; j++) {
        const float4* kj = (const float4*)(ks + j * HD);
        float acc = 0.f;
        #pragma unroll
        for (int d4 = 0; d4 < 8; d4++) {
            float4 kk = kj[d4];
            acc += qv[d4].x * kk.x + qv[d4].y * kk.y + qv[d4].z * kk.z + qv[d4].w * kk.w;
        }
        if (act) {
            int rj = j / WS, cj = j - rj * WS;
            float bias = biasv[(ri - rj + 6) * 13 + (ci - cj + 6)];
            float msk = (gi != grp[j]) ? -100.f : 0.f;
            ss[i * SSTR + j] = acc * SCALE + bias + msk;
        }
    }

    float inv = 0.f;
    if (act) {
        float mx = -1e30f;
        #pragma unroll 7
        for (int j = 0; j < Nn; j++) mx = fmaxf(mx, ss[i * SSTR + j]);
        float sm = 0.f;
        #pragma unroll 7
        for (int j = 0; j < Nn; j++) {
            float e = __expf(ss[i * SSTR + j] - mx);
            ss[i * SSTR + j] = e;
            sm += e;
        }
        inv = 1.f / sm;
    }

    float4 acc[8];
    #pragma unroll
    for (int d4 = 0; d4 < 8; d4++) acc[d4] = make_float4(0.f, 0.f, 0.f, 0.f);
    #pragma unroll 7
    for (int j = 0; j < Nn; j++) {
        const float4* vj = (const float4*)(vs + j * HD);
        float p = act ? ss[i * SSTR + j] : 0.f;
        #pragma unroll
        for (int d4 = 0; d4 < 8; d4++) {
            float4 vv = vj[d4];
            acc[d4].x = fmaf(p, vv.x, acc[d4].x);
            acc[d4].y = fmaf(p, vv.y, acc[d4].y);
            acc[d4].z = fmaf(p, vv.z, acc[d4].z);
            acc[d4].w = fmaf(p, vv.w, acc[d4].w);
        }
    }

    if (act) {
        size_t base = ((size_t)(b_ * Nn + i)) * Cc + head * HD;
        #pragma unroll
        for (int d4 = 0; d4 < 8; d4++) {
            float4 o = acc[d4];
            o.x *= inv; o.y *= inv; o.z *= inv; o.w *= inv;
            __nv_bfloat162 h0, h1, l0, l1;
            split2(o.x, h0.x, l0.x); split2(o.y, h0.y, l0.y);
            split2(o.z, h1.x, l1.x); split2(o.w, h1.y, l1.y);
            *(__nv_bfloat162*)(oh + base + d4 * 4)     = h0;
            *(__nv_bfloat162*)(oh + base + d4 * 4 + 2) = h1;
            *(__nv_bfloat162*)(ol + base + d4 * 4)     = l0;
            *(__nv_bfloat162*)(ol + base + d4 * 4 + 2) = l1;
        }
    }
}

// ---------------- launch ----------------
extern "C" void kernel_launch(void* const* d_in, const int* in_sizes, int n_in,
                              void* d_out, int out_size) {
    const float* x       = (const float*)d_in[0];
    const float* norm1_g = (const float*)d_in[1];
    const float* norm1_b = (const float*)d_in[2];
    const float* qkv_w   = (const float*)d_in[3];
    const float* qkv_b   = (const float*)d_in[4];
    const float* proj_w  = (const float*)d_in[5];
    const float* proj_b  = (const float*)d_in[6];
    const float* rpb     = (const float*)d_in[7];
    const float* norm2_g = (const float*)d_in[8];
    const float* norm2_b = (const float*)d_in[9];
    const float* fc1_w   = (const float*)d_in[10];
    const float* fc1_b   = (const float*)d_in[11];
    const float* fc2_w   = (const float*)d_in[12];
    const float* fc2_b   = (const float*)d_in[13];
    float* out = (float*)d_out;

    __nv_bfloat16 *xwh, *xwl, *aoh, *aol, *hidh, *hidl;
    __nv_bfloat16 *wqh, *wql, *wph, *wpl, *f1h, *f1l, *f2h, *f2l;
    float *qkv, *h;
    cudaGetSymbolAddress((void**)&xwh, g_xw_h);   cudaGetSymbolAddress((void**)&xwl, g_xw_l);
    cudaGetSymbolAddress((void**)&qkv, g_qkv);
    cudaGetSymbolAddress((void**)&aoh, g_ao_h);   cudaGetSymbolAddress((void**)&aol, g_ao_l);
    cudaGetSymbolAddress((void**)&h,   g_h);
    cudaGetSymbolAddress((void**)&hidh, g_hid_h); cudaGetSymbolAddress((void**)&hidl, g_hid_l);
    cudaGetSymbolAddress((void**)&wqh, g_wq_h);   cudaGetSymbolAddress((void**)&wql, g_wq_l);
    cudaGetSymbolAddress((void**)&wph, g_wp_h);   cudaGetSymbolAddress((void**)&wpl, g_wp_l);
    cudaGetSymbolAddress((void**)&f1h, g_f1_h);   cudaGetSymbolAddress((void**)&f1l, g_f1_l);
    cudaGetSymbolAddress((void**)&f2h, g_f2_h);   cudaGetSymbolAddress((void**)&f2l, g_f2_l);

    cudaFuncSetAttribute(gemm_mma<3 * Cc, Cc, 0>, cudaFuncAttributeMaxDynamicSharedMemorySize, SMEM_TOT);
    cudaFuncSetAttribute(gemm_mma<Cc, Cc, 2>,     cudaFuncAttributeMaxDynamicSharedMemorySize, SMEM_TOT);
    cudaFuncSetAttribute(gemm_mma<HID, Cc, 1>,    cudaFuncAttributeMaxDynamicSharedMemorySize, SMEM_TOT);
    cudaFuncSetAttribute(gemm_mma<Cc, HID, 3>,    cudaFuncAttributeMaxDynamicSharedMemorySize, SMEM_TOT);

    convert_kernel<<<(3 * Cc * Cc + 255) / 256, 256>>>(qkv_w, wqh, wql, 3 * Cc * Cc);
    convert_kernel<<<(Cc * Cc + 255) / 256, 256>>>(proj_w, wph, wpl, Cc * Cc);
    convert_kernel<<<(HID * Cc + 255) / 256, 256>>>(fc1_w, f1h, f1l, HID * Cc);
    convert_kernel<<<(Cc * HID + 255) / 256, 256>>>(fc2_w, f2h, f2l, Cc * HID);

    ln1_gather_kernel<<<ROWS / 8, 256>>>(x, norm1_g, norm1_b, xwh, xwl);

    gemm_mma<3 * Cc, Cc, 0><<<dim3(9, ROWS / 128), 256, SMEM_TOT>>>(
        xwh, xwl, wqh, wql, qkv_b, qkv, nullptr, nullptr, nullptr);

    attn_kernel<<<BW * NH, 64>>>(qkv, rpb, aoh, aol);

    gemm_mma<Cc, Cc, 2><<<dim3(3, ROWS / 128), 256, SMEM_TOT>>>(
        aoh, aol, wph, wpl, proj_b, h, x, nullptr, nullptr);

    ln_plain_kernel<<<ROWS / 8, 256>>>(h, norm2_g, norm2_b, xwh, xwl);

    gemm_mma<HID, Cc, 1><<<dim3(12, ROWS / 128), 256, SMEM_TOT>>>(
        xwh, xwl, f1h, f1l, fc1_b, nullptr, nullptr, hidh, hidl);

    gemm_mma<Cc, HID, 3><<<dim3(3, ROWS / 128), 256, SMEM_TOT>>>(
        hidh, hidl, f2h, f2l, fc2_b, out, h, nullptr, nullptr);
}